// round 8
// baseline (speedup 1.0000x reference)
#include <cuda_runtime.h>
#include <cuda_bf16.h>
#include <cstdint>

// Problem constants
#define Bq  16
#define Cq  128
#define HWq 1024
#define Nq  16384   // B*H*W
#define Dq  64
#define Kq  8192

#define ZQ_ELEMS 1048576          // Nq*Dq  (z_q_st output, NCHW)
#define DIFF_OFF 1048576
#define IND_OFF  1048577

#define EPSF 0.15f                // filter margin (~20 sigma of bf16 dot error)

// ---- scratch (device globals; no allocation allowed) ----
__device__ float          g_ze [Nq * Dq];   // projected+BN z_e fp32, [N][64]
__device__ __nv_bfloat16  g_zeb[Nq * Dq];   // z_e in bf16, [N][64]
__device__ __nv_bfloat16  g_eb [Kq * Dq];   // embed in bf16, [K][64]
__device__ float          g_ce [Kq];        // ||e_k||^2 (fp32, same chain as R3)
__device__ int            g_ind[Nq];        // argmin indices
__device__ float          g_part[256];      // per-block partials for diff

__device__ __forceinline__ void cpa16(uint32_t s, const void* g) {
    asm volatile("cp.async.ca.shared.global [%0], [%1], 16;" :: "r"(s), "l"(g));
}
#define CPA_COMMIT() asm volatile("cp.async.commit_group;")
#define CPA_WAIT2()  asm volatile("cp.async.wait_group 2;")

__device__ __forceinline__ void mma16816(float& c0, float& c1, float& c2, float& c3,
                                         unsigned a0, unsigned a1, unsigned a2,
                                         unsigned a3, unsigned b0, unsigned b1) {
    asm("mma.sync.aligned.m16n8k16.row.col.f32.bf16.bf16.f32 "
        "{%0,%1,%2,%3}, {%4,%5,%6,%7}, {%8,%9}, {%0,%1,%2,%3};"
        : "+f"(c0), "+f"(c1), "+f"(c2), "+f"(c3)
        : "r"(a0), "r"(a1), "r"(a2), "r"(a3), "r"(b0), "r"(b1));
}

// order-preserving float->uint (for packed 64-bit min keys)
__device__ __forceinline__ unsigned ordf(float f) {
    unsigned u = __float_as_uint(f);
    return (u & 0x80000000u) ? ~u : (u | 0x80000000u);
}

// ============================================================
// Kernel A: z_e = BN(conv1x1(z))  -> g_ze (fp32) and g_zeb (bf16)
// ============================================================
__global__ __launch_bounds__(256) void k_proj(
    const float* __restrict__ z,   const float* __restrict__ w,
    const float* __restrict__ pb,  const float* __restrict__ gma,
    const float* __restrict__ bta, const float* __restrict__ rmn,
    const float* __restrict__ rvr)
{
    __shared__ float zsm[Cq * 32];   // [c][nn]
    __shared__ float wsm[Dq * Cq];   // [d][c]
    int tid = threadIdx.x;
    int n0  = blockIdx.x * 32;
    int b   = n0 >> 10, hw0 = n0 & 1023;

#pragma unroll
    for (int i = 0; i < 16; i++) {
        int idx = tid + i * 256;
        int c = idx >> 5, nn = idx & 31;
        zsm[idx] = z[(b * Cq + c) * HWq + hw0 + nn];
    }
#pragma unroll
    for (int i = 0; i < 32; i++) wsm[tid + i * 256] = w[tid + i * 256];
    __syncthreads();

    int lane = tid & 31, wd = tid >> 5;
    int d0 = wd * 8;
    float acc[8];
#pragma unroll
    for (int j = 0; j < 8; j++) acc[j] = 0.f;

#pragma unroll 4
    for (int c = 0; c < Cq; c++) {
        float a = zsm[c * 32 + lane];
#pragma unroll
        for (int j = 0; j < 8; j++)
            acc[j] = fmaf(a, wsm[(d0 + j) * Cq + c], acc[j]);
    }

    float o[8];
#pragma unroll
    for (int j = 0; j < 8; j++) {
        int d = d0 + j;
        float sc = gma[d] * (1.0f / sqrtf(rvr[d] + 1e-5f));
        float sh = bta[d] - rmn[d] * sc;
        o[j] = (acc[j] + pb[d]) * sc + sh;
    }
    float* dst = g_ze + (size_t)(n0 + lane) * Dq + d0;
    ((float4*)dst)[0] = make_float4(o[0], o[1], o[2], o[3]);
    ((float4*)dst)[1] = make_float4(o[4], o[5], o[6], o[7]);

    __nv_bfloat162 p[4];
#pragma unroll
    for (int j = 0; j < 4; j++)
        p[j] = __float22bfloat162_rn(make_float2(o[2 * j], o[2 * j + 1]));
    *(uint4*)(g_zeb + (size_t)(n0 + lane) * Dq + d0) = *(uint4*)p;
}

// ============================================================
// Kernel P: embed -> g_eb (bf16) and ce[k]=||e_k||^2 (fp32)
// ============================================================
__global__ __launch_bounds__(256) void k_prep(const float* __restrict__ embed)
{
    int id  = blockIdx.x * 256 + threadIdx.x;   // [0, Kq*16)
    int k   = id >> 4, seg = id & 15;
    float4 v = ((const float4*)embed)[id];
    __nv_bfloat162 b0 = __float22bfloat162_rn(make_float2(v.x, v.y));
    __nv_bfloat162 b1 = __float22bfloat162_rn(make_float2(v.z, v.w));
    uint2 pk; pk.x = *(unsigned*)&b0; pk.y = *(unsigned*)&b1;
    *(uint2*)(g_eb + (size_t)k * Dq + seg * 4) = pk;

    float s = v.x * v.x + v.y * v.y + v.z * v.z + v.w * v.w;
    s += __shfl_xor_sync(0xffffffffu, s, 1);
    s += __shfl_xor_sync(0xffffffffu, s, 2);
    s += __shfl_xor_sync(0xffffffffu, s, 4);
    s += __shfl_xor_sync(0xffffffffu, s, 8);
    if (seg == 0) g_ce[k] = s;
}

// ============================================================
// Kernel C: argmin via bf16 MMA + running-threshold exact rescore
// Single sweep. 4-stage cp.async ring, ONE barrier per chunk.
// CTA: 64 rows x all K. 8 warps: (w%4) -> m16 tile, (w/4) -> 32-code half.
// ============================================================

// smem byte offsets (16B aligned)
#define SM_ZS    0        // fp32 z tile   [64][68]f      -> 17408 B
#define SM_ZSB   17408    // bf16 z tile   [64][72]bf16   ->  9216 B
#define SM_EB    26624    // bf16 e chunk  4x[64][72]     -> 36864 B
#define SM_CE    63488    // ce chunk      4x64 f         ->  1024 B
#define SM_KEYS  64512    // ull[64]                      ->   512 B
#define SM_SZZ   65024    // float[64]                    ->   256 B
#define SM_TOTAL 65280
#define EBBUF    9216

__device__ __forceinline__ void rescore(const float* zr, float szzr,
                                        const float* __restrict__ embed,
                                        int kglob, unsigned long long* keyp)
{
    const float* er = embed + (size_t)kglob * Dq;
    float lo = 0.f, hi = 0.f;
#pragma unroll
    for (int d = 0; d < 32; d++) {          // even/odd split, same chain as R3
        lo = fmaf(zr[2 * d],     __ldg(er + 2 * d),     lo);
        hi = fmaf(zr[2 * d + 1], __ldg(er + 2 * d + 1), hi);
    }
    float m = fmaf(-2.0f, lo + hi, szzr) + __ldg(&g_ce[kglob]);
    unsigned long long key =
        ((unsigned long long)ordf(m) << 32) | (unsigned)kglob;
    atomicMin(keyp, key);
}

__global__ __launch_bounds__(256, 2) void k_argmin(const float* __restrict__ embed)
{
    extern __shared__ char sm[];
    float*              zs   = (float*)(sm + SM_ZS);
    char*               zsbB = sm + SM_ZSB;
    char*               ebB  = sm + SM_EB;
    float*              cesm = (float*)(sm + SM_CE);
    unsigned long long* keys = (unsigned long long*)(sm + SM_KEYS);
    float*              szz  = (float*)(sm + SM_SZZ);
    uint32_t smemu = (uint32_t)__cvta_generic_to_shared(sm);

    int tid = threadIdx.x;
    int l   = tid & 31, w = tid >> 5;
    int n0  = blockIdx.x * 64;
    int mbase = (w & 3) * 16;           // m16 tile
    int nhalf = (w >> 2) * 32;          // 32-code half of chunk
    int lg = l >> 2, lq = l & 3;        // fragment coords

    // prefetch helper (chunk c -> ring buffer c&3)
    auto prefetch = [&](int c) {
        int buf = c & 3;
#pragma unroll
        for (int i = 0; i < 2; i++) {
            int g = tid + i * 256;          // 0..511
            int code = g >> 3, seg = g & 7;
            cpa16(smemu + SM_EB + buf * EBBUF + code * 144 + seg * 16,
                  g_eb + (size_t)(c * 64 + code) * Dq + seg * 8);
        }
        if (tid < 16)
            cpa16(smemu + SM_CE + buf * 256 + tid * 16, g_ce + c * 64 + tid * 4);
    };

    prefetch(0); CPA_COMMIT();
    prefetch(1); CPA_COMMIT();
    prefetch(2); CPA_COMMIT();

    // ---- load z tiles ----
#pragma unroll
    for (int i = 0; i < 4; i++) {       // fp32 [64][68]
        int id = tid + i * 256;
        int r = id >> 4, s = id & 15;
        *(float4*)(zs + r * 68 + s * 4) =
            *(const float4*)(g_ze + (size_t)(n0 + r) * Dq + s * 4);
    }
#pragma unroll
    for (int i = 0; i < 2; i++) {       // bf16 [64][72]
        int g = tid + i * 256;
        int r = g >> 3, s = g & 7;
        *(uint4*)(zsbB + r * 144 + s * 16) =
            *(const uint4*)(g_zeb + (size_t)(n0 + r) * Dq + s * 8);
    }
    if (tid < 64) keys[tid] = ~0ull;
    __syncthreads();
    if (tid < 64) {
        const float* r = zs + tid * 68;
        float s = 0.f;
#pragma unroll
        for (int d = 0; d < Dq; d++) s = fmaf(r[d], r[d], s);
        szz[tid] = s;
    }
    // szz visibility for rescores: covered by the first in-loop __syncthreads.

    float run0 = 3.0e38f, run1 = 3.0e38f;   // running approx minima (2 rows)
    int   r0 = mbase + lg, r1 = r0 + 8;

    for (int c = 0; c < 128; c++) {
        CPA_WAIT2();
        __syncthreads();      // all warps done with chunk c-1; chunk c data ready
        if (c + 3 < 128) prefetch(c + 3);   // refills buf (c-1)&3 -- safe now
        CPA_COMMIT();

        int buf = c & 3;
        const char*  eb = ebB + buf * EBBUF;
        const float* ce = cesm + buf * 64;

        // A fragments (shared across n-tiles)
        unsigned af[4][4];
#pragma unroll
        for (int ks = 0; ks < 4; ks++) {
            int cb = (ks * 16 + lq * 2) * 2;       // byte col
            af[ks][0] = *(const unsigned*)(zsbB + r0 * 144 + cb);
            af[ks][1] = *(const unsigned*)(zsbB + r1 * 144 + cb);
            af[ks][2] = *(const unsigned*)(zsbB + r0 * 144 + cb + 16);
            af[ks][3] = *(const unsigned*)(zsbB + r1 * 144 + cb + 16);
        }

#pragma unroll
        for (int nt = 0; nt < 4; nt++) {
            float c0 = 0.f, c1 = 0.f, c2 = 0.f, c3 = 0.f;
            int crow = nhalf + nt * 8 + lg;
#pragma unroll
            for (int ks = 0; ks < 4; ks++) {
                int cb = (ks * 16 + lq * 2) * 2;
                unsigned b0 = *(const unsigned*)(eb + crow * 144 + cb);
                unsigned b1 = *(const unsigned*)(eb + crow * 144 + cb + 16);
                mma16816(c0, c1, c2, c3,
                         af[ks][0], af[ks][1], af[ks][2], af[ks][3], b0, b1);
            }
            int cloc = nhalf + nt * 8 + 2 * lq;    // this thread's code pair
            float2 cp = *(const float2*)(ce + cloc);
            float s0 = fmaf(-2.f, c0, cp.x);
            float s1 = fmaf(-2.f, c1, cp.y);
            float s2 = fmaf(-2.f, c2, cp.x);
            float s3 = fmaf(-2.f, c3, cp.y);

            // quad-reduce (4 lanes sharing each row) then update running min
            float q0 = fminf(s0, s1);
            q0 = fminf(q0, __shfl_xor_sync(0xffffffffu, q0, 1));
            q0 = fminf(q0, __shfl_xor_sync(0xffffffffu, q0, 2));
            run0 = fminf(run0, q0);
            float q1 = fminf(s2, s3);
            q1 = fminf(q1, __shfl_xor_sync(0xffffffffu, q1, 1));
            q1 = fminf(q1, __shfl_xor_sync(0xffffffffu, q1, 2));
            run1 = fminf(run1, q1);

            // exact rescore of anything within EPS of the running min.
            // run >= final min always => true argmin is always rescored.
            int kb = c * 64 + cloc;
            float t0 = run0 + EPSF, t1 = run1 + EPSF;
            if (s0 <= t0) rescore(zs + r0 * 68, szz[r0], embed, kb,     &keys[r0]);
            if (s1 <= t0) rescore(zs + r0 * 68, szz[r0], embed, kb + 1, &keys[r0]);
            if (s2 <= t1) rescore(zs + r1 * 68, szz[r1], embed, kb,     &keys[r1]);
            if (s3 <= t1) rescore(zs + r1 * 68, szz[r1], embed, kb + 1, &keys[r1]);
        }
    }

    __syncthreads();
    if (tid < 64) g_ind[n0 + tid] = (int)(keys[tid] & 0xFFFFFFFFu);
}

// ============================================================
// Kernel D: gather z_q, straight-through out (NCHW), ind, diff partials
// ============================================================
__global__ __launch_bounds__(64) void k_out(const float* __restrict__ embed,
                                            float* __restrict__ out, int out_size)
{
    __shared__ float red[64];
    int tid = threadIdx.x;
    int n   = blockIdx.x * 64 + tid;
    int b   = n >> 10, hw = n & 1023;
    int ind = g_ind[n];
    const float4* q4 = (const float4*)(embed + (size_t)ind * Dq);
    const float4* e4 = (const float4*)(g_ze + (size_t)n * Dq);
    float* ob = out + b * 65536 + hw;
    bool wrq = (out_size >= ZQ_ELEMS);
    float ss = 0.f;
#pragma unroll
    for (int i = 0; i < 16; i++) {
        float4 q = q4[i], e = e4[i];
        float dx = q.x - e.x, dy = q.y - e.y, dz = q.z - e.z, dw = q.w - e.w;
        ss += dx * dx + dy * dy + dz * dz + dw * dw;
        if (wrq) {
            ob[(4 * i + 0) * 1024] = e.x + dx;
            ob[(4 * i + 1) * 1024] = e.y + dy;
            ob[(4 * i + 2) * 1024] = e.z + dz;
            ob[(4 * i + 3) * 1024] = e.w + dw;
        }
    }
    if (out_size >= IND_OFF + Nq) out[IND_OFF + n] = (float)ind;

    red[tid] = ss;
    __syncthreads();
    for (int s = 32; s; s >>= 1) {
        if (tid < s) red[tid] += red[tid + s];
        __syncthreads();
    }
    if (tid == 0) g_part[blockIdx.x] = red[0];
}

// ============================================================
// Kernel E: deterministic final reduce -> diff scalar
// ============================================================
__global__ void k_diff(float* __restrict__ out, int out_size) {
    if (threadIdx.x == 0 && out_size >= DIFF_OFF + 1) {
        float s = 0.f;
        for (int i = 0; i < 256; i++) s += g_part[i];
        float m = s * (1.0f / 1048576.0f);           // mean over B*H*W*D
        out[DIFF_OFF] = 10.0f * (0.25f * m + m);     // KLD_SCALE*(COMMIT*m + m)
    }
}

extern "C" void kernel_launch(void* const* d_in, const int* in_sizes, int n_in,
                              void* d_out, int out_size)
{
    const float* z     = (const float*)d_in[0];   // [16,128,32,32]
    const float* pw    = (const float*)d_in[1];   // [64,128]
    const float* pb    = (const float*)d_in[2];   // [64]
    const float* gma   = (const float*)d_in[3];   // [64]
    const float* bta   = (const float*)d_in[4];   // [64]
    const float* rmn   = (const float*)d_in[5];   // [64]
    const float* rvr   = (const float*)d_in[6];   // [64]
    const float* embed = (const float*)d_in[7];   // [8192,64]
    float* out = (float*)d_out;

    cudaFuncSetAttribute(k_argmin, cudaFuncAttributeMaxDynamicSharedMemorySize,
                         SM_TOTAL);

    k_proj  <<<Nq / 32, 256>>>(z, pw, pb, gma, bta, rmn, rvr);
    k_prep  <<<Kq * 16 / 256, 256>>>(embed);
    k_argmin<<<Nq / 64, 256, SM_TOTAL>>>(embed);
    k_out   <<<Nq / 64, 64>>>(embed, out, out_size);
    k_diff  <<<1, 32>>>(out, out_size);
}